// round 16
// baseline (speedup 1.0000x reference)
#include <cuda_runtime.h>
#include <cuda_fp16.h>
#include <cstdint>

#define LSEQ   256
#define NSEQ   128
#define DMODEL 256
#define HEADS  8
#define DHEAD  32
#define PDIM   128
#define MROWS  (NSEQ * LSEQ)   // 32768

// ---------------------------------------------------------------------------
// Scratch (device globals; allocation-free, graph-capture safe)
// ---------------------------------------------------------------------------
__device__ __align__(16) __half g_msa_h[MROWS * DMODEL];        // fp16 msa [32768][256]
__device__ __align__(16) __half g_wqkv_t[3 * DMODEL * DMODEL];  // [768][256]  (N-major, K contiguous)
__device__ __align__(16) __half g_wout_t[DMODEL * DMODEL];      // [256][256]
__device__ __align__(16) __half g_qkv_h[MROWS * 3 * DMODEL];    // [32768][768]  (q prescaled by scale*log2e)
__device__ __align__(16) __half g_att_h[MROWS * DMODEL];        // [32768][256]
__device__ float g_bias[HEADS * LSEQ * LSEQ];                   // [h][q][k]  (already * log2e)

// ---------------------------------------------------------------------------
// helpers
// ---------------------------------------------------------------------------
__device__ __forceinline__ uint32_t smem_u32(const void* p) {
    uint32_t a;
    asm("{ .reg .u64 t; cvta.to.shared.u64 t, %1; cvt.u32.u64 %0, t; }" : "=r"(a) : "l"(p));
    return a;
}

#define LDMX4(r0, r1, r2, r3, addr)                                           \
    asm volatile("ldmatrix.sync.aligned.m8n8.x4.shared.b16 {%0,%1,%2,%3}, [%4];" \
                 : "=r"(r0), "=r"(r1), "=r"(r2), "=r"(r3) : "r"(addr))

#define LDMX4T(r0, r1, r2, r3, addr)                                          \
    asm volatile("ldmatrix.sync.aligned.m8n8.x4.trans.shared.b16 {%0,%1,%2,%3}, [%4];" \
                 : "=r"(r0), "=r"(r1), "=r"(r2), "=r"(r3) : "r"(addr))

__device__ __forceinline__ void mma16816(float* c, const uint32_t* a, const uint32_t* b) {
    asm volatile("mma.sync.aligned.m16n8k16.row.col.f32.f16.f16.f32 "
                 "{%0,%1,%2,%3}, {%4,%5,%6,%7}, {%8,%9}, {%0,%1,%2,%3};"
                 : "+f"(c[0]), "+f"(c[1]), "+f"(c[2]), "+f"(c[3])
                 : "r"(a[0]), "r"(a[1]), "r"(a[2]), "r"(a[3]), "r"(b[0]), "r"(b[1]));
}

#define CP_ASYNC16(dst, src) \
    asm volatile("cp.async.cg.shared.global [%0], [%1], 16;" :: "r"(dst), "l"(src))
#define CP_COMMIT() asm volatile("cp.async.commit_group;" ::: "memory")
#define CP_WAIT(n)  asm volatile("cp.async.wait_group %0;" :: "n"(n) : "memory")

// ---------------------------------------------------------------------------
// HMMA GEMM, cp.async 3-stage pipeline: C[M,N] = A[M,256] @ Bt[N,256]^T.
// Block tile 64(M)x128(N); K chunked by 64. 8 warps each 16(M)x64(N).
// ---------------------------------------------------------------------------
template <bool FINAL>
__global__ void __launch_bounds__(256) gemm_hmma(
    const __half* __restrict__ A, const __half* __restrict__ Bt,
    __half* __restrict__ Ch, float* __restrict__ Cf,
    const float* __restrict__ bias, int ldc, float qscale)
{
    extern __shared__ __align__(16) char sm[];  // 3 stages x (A 8KB + B 16KB)

    const int tid = threadIdx.x;
    const int wid = tid >> 5, lane = tid & 31;
    const int m0 = blockIdx.y << 6;
    const int n0 = blockIdx.x << 7;
    const uint32_t smbase = smem_u32(sm);

    auto load_stage = [&](int s, int kc) {
        const uint32_t base = smbase + s * 24576;
#pragma unroll
        for (int i = 0; i < 6; i++) {
            const int idx = tid + i * 256;   // 0..1535
            if (idx < 512) {
                const int r = idx >> 3, c = idx & 7;
                const __half* src = A + (size_t)(m0 + r) * 256 + kc * 64 + c * 8;
                CP_ASYNC16(base + r * 128 + ((c ^ (r & 7)) << 4), src);
            } else {
                const int j = idx - 512;
                const int r = j >> 3, c = j & 7;
                const __half* src = Bt + (size_t)(n0 + r) * 256 + kc * 64 + c * 8;
                CP_ASYNC16(base + 8192 + r * 128 + ((c ^ (r & 7)) << 4), src);
            }
        }
        CP_COMMIT();
    };

    const int wm = (wid >> 1) << 4;    // 0,16,32,48
    const int wn = (wid & 1) << 6;     // 0,64
    const int a_row = (lane & 7) + ((lane >> 3) & 1) * 8;
    const int a_cadd = lane >> 4;
    const int b_row = (lane & 7) + ((lane >> 4) & 1) * 8;
    const int b_cadd = (lane >> 3) & 1;

    const int a_r = wm + a_row;
    int b_r[4];
#pragma unroll
    for (int j = 0; j < 4; j++) b_r[j] = wn + 16 * j + b_row;

    float acc[8][4];
#pragma unroll
    for (int j = 0; j < 8; j++)
#pragma unroll
        for (int t = 0; t < 4; t++) acc[j][t] = 0.f;

    auto compute_chunk = [&](int s) {
        const uint32_t baseA = smbase + s * 24576;
        const uint32_t baseB = baseA + 8192;
#pragma unroll
        for (int kk = 0; kk < 4; kk++) {
            const int k8 = kk * 2;
            uint32_t a[4];
            {
                const uint32_t addr = baseA + a_r * 128 +
                                      (((k8 + a_cadd) ^ (a_r & 7)) << 4);
                LDMX4(a[0], a[1], a[2], a[3], addr);
            }
            uint32_t b[8][2];
#pragma unroll
            for (int j = 0; j < 4; j++) {
                const uint32_t addr = baseB + b_r[j] * 128 +
                                      (((k8 + b_cadd) ^ (b_r[j] & 7)) << 4);
                LDMX4(b[2 * j][0], b[2 * j][1], b[2 * j + 1][0], b[2 * j + 1][1], addr);
            }
#pragma unroll
            for (int j = 0; j < 8; j++)
                mma16816(acc[j], a, b[j]);
        }
    };

    load_stage(0, 0);
    load_stage(1, 1);
    load_stage(2, 2);

    CP_WAIT(2); __syncthreads();
    compute_chunk(0);
    __syncthreads();
    load_stage(0, 3);

    CP_WAIT(2); __syncthreads();
    compute_chunk(1);

    CP_WAIT(1); __syncthreads();
    compute_chunk(2);

    CP_WAIT(0); __syncthreads();
    compute_chunk(0);

    const int tr = lane >> 2;
    const int tc = (lane & 3) * 2;
    const int row = m0 + wm + tr;
#pragma unroll
    for (int j = 0; j < 8; j++) {
        const int col = n0 + wn + 8 * j + tc;
        if (FINAL) {
            const float b0 = __ldg(&bias[col]), b1 = __ldg(&bias[col + 1]);
            float2 v0 = make_float2(acc[j][0] + b0, acc[j][1] + b1);
            float2 v1 = make_float2(acc[j][2] + b0, acc[j][3] + b1);
            *(float2*)(Cf + (size_t)row * ldc + col) = v0;
            *(float2*)(Cf + (size_t)(row + 8) * ldc + col) = v1;
        } else {
            const float qs = (col < 256) ? qscale : 1.0f;
            __half2 h0 = __floats2half2_rn(acc[j][0] * qs, acc[j][1] * qs);
            __half2 h1 = __floats2half2_rn(acc[j][2] * qs, acc[j][3] * qs);
            *(__half2*)(Ch + (size_t)row * ldc + col) = h0;
            *(__half2*)(Ch + (size_t)(row + 8) * ldc + col) = h1;
        }
    }
}

// ---------------------------------------------------------------------------
// Merged conversion kernel: blocks [0,2048) convert msa (fp32->fp16),
// blocks [2048,2816) transpose+convert w_qkv, blocks [2816,3072) w_out.
// ---------------------------------------------------------------------------
__global__ void __launch_bounds__(256) cvt_all_kernel(
    const float* __restrict__ msa, const float* __restrict__ w_qkv,
    const float* __restrict__ w_out, __half* __restrict__ msa_h,
    __half* __restrict__ wqkv_t, __half* __restrict__ wout_t)
{
    const int b = blockIdx.x;
    const int tid = threadIdx.x;
    if (b < 2048) {
        const float4* in = (const float4*)msa;
        __half2* out = (__half2*)msa_h;
        const int n4 = MROWS * DMODEL / 4;   // 2097152
#pragma unroll
        for (int it = 0; it < 4; it++) {
            const int i = b * 256 + tid + it * 524288;
            if (i < n4) {
                float4 v = in[i];
                out[2 * i]     = __floats2half2_rn(v.x, v.y);
                out[2 * i + 1] = __floats2half2_rn(v.z, v.w);
            }
        }
    } else if (b < 2816) {
        const int idx = (b - 2048) * 256 + tid;   // < 768*256 = 196608
        const int n = idx >> 8, k = idx & 255;
        wqkv_t[idx] = __float2half(w_qkv[k * (3 * DMODEL) + n]);
    } else {
        const int idx = (b - 2816) * 256 + tid;   // < 65536
        const int n = idx >> 8, k = idx & 255;
        wout_t[idx] = __float2half(w_out[k * DMODEL + n]);
    }
}

// ---------------------------------------------------------------------------
// pair_bias: bias[h][q][k] = (sum_p pair[q][k][p] * w_pb[p][h] + b_pb[h]) * log2e
// ---------------------------------------------------------------------------
__global__ void __launch_bounds__(256) pair_bias_kernel(
    const float* __restrict__ pair, const float* __restrict__ w_pb,
    const float* __restrict__ b_pb, float* __restrict__ bias_out)
{
    __shared__ float w[PDIM * HEADS];
    __shared__ float bb[HEADS];
    const int tid = threadIdx.x;
    for (int i = tid; i < PDIM * HEADS; i += 256) w[i] = w_pb[i];
    if (tid < HEADS) bb[tid] = b_pb[tid];
    __syncthreads();

    const int warp = (blockIdx.x << 3) + (tid >> 5);
    const int lane = tid & 31;
    const int q = warp >> 8;
    const int k = warp & 255;

    float4 p = *(const float4*)(pair + ((size_t)(q << 8) + k) * PDIM + (lane << 2));
    const int p0 = lane << 2;
    const float LOG2E = 1.4426950408889634f;

    float res[HEADS];
#pragma unroll
    for (int h = 0; h < HEADS; h++) {
        float s = p.x * w[(p0 + 0) * HEADS + h]
                + p.y * w[(p0 + 1) * HEADS + h]
                + p.z * w[(p0 + 2) * HEADS + h]
                + p.w * w[(p0 + 3) * HEADS + h];
#pragma unroll
        for (int off = 16; off; off >>= 1)
            s += __shfl_xor_sync(0xFFFFFFFFu, s, off);
        res[h] = (s + bb[h]) * LOG2E;
    }
    if (lane == 0) {
#pragma unroll
        for (int h = 0; h < HEADS; h++)
            bias_out[((size_t)(h << 8) + q) * LSEQ + k] = res[h];
    }
}

// ---------------------------------------------------------------------------
// Attention v7: HMMA flash-attention; each warp owns 32 q-rows (two 16-row
// m-tiles) so K/V ldmatrix fragments are amortized 2x (LDSM was the measured
// bottleneck: L1=70%). CTA = 4 warps = 128 q-rows; grid 2048. The two m-tiles
// are processed sequentially per chunk to cap live registers.
// ---------------------------------------------------------------------------
__global__ void __launch_bounds__(128) attn_kernel(
    const int* __restrict__ mask, const __half* __restrict__ qkv,
    const float* __restrict__ bias, __half* __restrict__ outh)
{
    extern __shared__ __align__(16) __half smh[];
    __half* Qs = smh;                  // 128 rows x 40 halfs (80B pitch)
    __half* Ks = smh + 5120;           // 256 x 40
    __half* Vs = smh + 15360;          // 256 x 40
    float* mneg = (float*)(smh + 25600);  // 256 floats: 0 or -16384

    const int bx = blockIdx.x;
    const int n = bx >> 4;
    const int h = (bx >> 1) & 7;
    const int qb = (bx & 1) << 7;      // 0 or 128
    const int tid = threadIdx.x;
    const int wid = tid >> 5, lane = tid & 31;

    const __half* basep = qkv + (size_t)(n * LSEQ) * 768 + h * DHEAD;
    for (int u = tid; u < 1024; u += 128) {
        const int l = u >> 2, c = u & 3;
        const __half* r = basep + (size_t)l * 768 + c * 8;
        *(uint4*)&Ks[l * 40 + c * 8] = *(const uint4*)(r + 256);
        *(uint4*)&Vs[l * 40 + c * 8] = *(const uint4*)(r + 512);
    }
    for (int u = tid; u < 512; u += 128) {
        const int l = u >> 2, c = u & 3;
        *(uint4*)&Qs[l * 40 + c * 8] = *(const uint4*)(basep + (size_t)(qb + l) * 768 + c * 8);
    }
    mneg[tid] = mask[n * LSEQ + tid] ? 0.0f : -16384.0f;
    mneg[tid + 128] = mask[n * LSEQ + tid + 128] ? 0.0f : -16384.0f;
    __syncthreads();

    const uint32_t Qa = smem_u32(Qs), Ka = smem_u32(Ks), Va = smem_u32(Vs);
    const int wq0 = wid * 32;          // warp covers q rows [wq0, wq0+32)
    const int a_row = (lane & 7) + ((lane >> 3) & 1) * 8;
    const int a_c = lane >> 4;
    const int b_row = (lane & 7) + ((lane >> 4) & 1) * 8;
    const int b_c = (lane >> 3) & 1;
    const int tr = lane >> 2, tc = (lane & 3) * 2;

    // Q fragments for both m-tiles (persistent)
    uint32_t aq[2][2][4];
#pragma unroll
    for (int m = 0; m < 2; m++)
#pragma unroll
        for (int kt = 0; kt < 2; kt++) {
            const uint32_t addr = Qa + (wq0 + m * 16 + a_row) * 80 + (kt * 2 + a_c) * 16;
            LDMX4(aq[m][kt][0], aq[m][kt][1], aq[m][kt][2], aq[m][kt][3], addr);
        }

    float o[2][4][4];
#pragma unroll
    for (int m = 0; m < 2; m++)
#pragma unroll
        for (int nt = 0; nt < 4; nt++)
#pragma unroll
            for (int t = 0; t < 4; t++) o[m][nt][t] = 0.f;
    float rsum[2][2] = {{0.f, 0.f}, {0.f, 0.f}};
    float rmax[2][2] = {{-1e30f, -1e30f}, {-1e30f, -1e30f}};

    const float* bias_h = bias + (size_t)h * LSEQ * LSEQ;  // [q][k]
    const float* br[2];
    br[0] = bias_h + (size_t)(qb + wq0 + tr) * 256;
    br[1] = br[0] + 16 * 256;

#pragma unroll
    for (int j = 0; j < 8; j++) {
        const int kb = j * 32;

        // mask adders (shared by both m-tiles)
        float2 mn[4];
#pragma unroll
        for (int nn = 0; nn < 4; nn++)
            mn[nn] = *(float2*)&mneg[kb + nn * 8 + tc];

        // K fragments (shared)
        uint32_t bk[2][2][4];
#pragma unroll
        for (int kg = 0; kg < 2; kg++)
#pragma unroll
            for (int kt = 0; kt < 2; kt++) {
                const uint32_t addr = Ka + (kb + kg * 16 + b_row) * 80 + (kt * 2 + b_c) * 16;
                LDMX4(bk[kg][kt][0], bk[kg][kt][1], bk[kg][kt][2], bk[kg][kt][3], addr);
            }

        // V fragments (shared)
        uint32_t bv[2][4][2];
#pragma unroll
        for (int kg = 0; kg < 2; kg++)
#pragma unroll
            for (int dh = 0; dh < 2; dh++) {
                uint32_t r0, r1, r2, r3;
                const uint32_t addr = Va + (kb + kg * 16 + a_row) * 80 + (dh * 2 + a_c) * 16;
                LDMX4T(r0, r1, r2, r3, addr);
                bv[kg][dh * 2][0] = r0;     bv[kg][dh * 2][1] = r1;
                bv[kg][dh * 2 + 1][0] = r2; bv[kg][dh * 2 + 1][1] = r3;
            }

        // two independent m-tiles, processed sequentially (register cap)
#pragma unroll
        for (int m = 0; m < 2; m++) {
            float2 b0[4], b1[4];
#pragma unroll
            for (int nn = 0; nn < 4; nn++) {
                const int kc = kb + nn * 8 + tc;
                b0[nn] = *(const float2*)(br[m] + kc);
                b1[nn] = *(const float2*)(br[m] + 8 * 256 + kc);
            }

            float s[4][4];
#pragma unroll
            for (int nn = 0; nn < 4; nn++) {
#pragma unroll
                for (int t = 0; t < 4; t++) s[nn][t] = 0.f;
#pragma unroll
                for (int kt = 0; kt < 2; kt++)
                    mma16816(s[nn], aq[m][kt], &bk[nn >> 1][kt][(nn & 1) * 2]);
            }

            float cmax[2] = {-1e30f, -1e30f};
#pragma unroll
            for (int nn = 0; nn < 4; nn++) {
                s[nn][0] += b0[nn].x + mn[nn].x;
                s[nn][1] += b0[nn].y + mn[nn].y;
                s[nn][2] += b1[nn].x + mn[nn].x;
                s[nn][3] += b1[nn].y + mn[nn].y;
                cmax[0] = fmaxf(cmax[0], fmaxf(s[nn][0], s[nn][1]));
                cmax[1] = fmaxf(cmax[1], fmaxf(s[nn][2], s[nn][3]));
            }

            float sf[2];
#pragma unroll
            for (int r = 0; r < 2; r++) {
                float v = cmax[r];
                v = fmaxf(v, __shfl_xor_sync(0xFFFFFFFFu, v, 1));
                v = fmaxf(v, __shfl_xor_sync(0xFFFFFFFFu, v, 2));
                const float mnew = fmaxf(rmax[m][r], v);
                sf[r] = exp2f(rmax[m][r] - mnew);
                rmax[m][r] = mnew;
                rsum[m][r] *= sf[r];
            }
#pragma unroll
            for (int nt = 0; nt < 4; nt++) {
                o[m][nt][0] *= sf[0]; o[m][nt][1] *= sf[0];
                o[m][nt][2] *= sf[1]; o[m][nt][3] *= sf[1];
            }

            uint32_t ap[2][4];
#pragma unroll
            for (int nn = 0; nn < 4; nn++) {
                float p0 = exp2f(s[nn][0] - rmax[m][0]);
                float p1 = exp2f(s[nn][1] - rmax[m][0]);
                float p2 = exp2f(s[nn][2] - rmax[m][1]);
                float p3 = exp2f(s[nn][3] - rmax[m][1]);
                rsum[m][0] += p0 + p1;
                rsum[m][1] += p2 + p3;
                __half2 h01 = __floats2half2_rn(p0, p1);
                __half2 h23 = __floats2half2_rn(p2, p3);
                const int kg = nn >> 1, half_ = (nn & 1) * 2;
                ap[kg][half_ + 0] = *(uint32_t*)&h01;
                ap[kg][half_ + 1] = *(uint32_t*)&h23;
            }

#pragma unroll
            for (int nt = 0; nt < 4; nt++)
#pragma unroll
                for (int kg = 0; kg < 2; kg++)
                    mma16816(o[m][nt], ap[kg], bv[kg][nt]);
        }
    }

    // normalize and store both m-tiles
#pragma unroll
    for (int m = 0; m < 2; m++) {
        float inv[2];
#pragma unroll
        for (int r = 0; r < 2; r++) {
            float v = rsum[m][r];
            v += __shfl_xor_sync(0xFFFFFFFFu, v, 1);
            v += __shfl_xor_sync(0xFFFFFFFFu, v, 2);
            inv[r] = (v > 0.f) ? (1.0f / v) : 0.f;
        }
        const size_t q0 = (size_t)(n * LSEQ + qb + wq0 + m * 16 + tr);
        const int dcol = h * DHEAD + tc;
#pragma unroll
        for (int nt = 0; nt < 4; nt++) {
            __half2 h0 = __floats2half2_rn(o[m][nt][0] * inv[0], o[m][nt][1] * inv[0]);
            __half2 h1 = __floats2half2_rn(o[m][nt][2] * inv[1], o[m][nt][3] * inv[1]);
            *(__half2*)(outh + q0 * DMODEL + dcol + nt * 8) = h0;
            *(__half2*)(outh + (q0 + 8) * DMODEL + dcol + nt * 8) = h1;
        }
    }
}

// ---------------------------------------------------------------------------
// Launch: single stream, 5 kernels; attn stays in profile slot #4.
// ---------------------------------------------------------------------------
extern "C" void kernel_launch(void* const* d_in, const int* in_sizes, int n_in,
                              void* d_out, int out_size)
{
    const float* msa   = (const float*)d_in[0];
    const float* pair  = (const float*)d_in[1];
    const int*   mask  = (const int*)d_in[2];
    const float* w_qkv = (const float*)d_in[3];
    const float* w_pb  = (const float*)d_in[4];
    const float* b_pb  = (const float*)d_in[5];
    const float* w_out = (const float*)d_in[6];
    const float* b_out = (const float*)d_in[7];
    float* out = (float*)d_out;

    __half *msa_h, *wqkv_t, *wout_t, *qkv_h, *att_h;
    float* bias_ptr;
    cudaGetSymbolAddress((void**)&msa_h,   g_msa_h);
    cudaGetSymbolAddress((void**)&wqkv_t,  g_wqkv_t);
    cudaGetSymbolAddress((void**)&wout_t,  g_wout_t);
    cudaGetSymbolAddress((void**)&qkv_h,   g_qkv_h);
    cudaGetSymbolAddress((void**)&att_h,   g_att_h);
    cudaGetSymbolAddress((void**)&bias_ptr, g_bias);

    const int gemm_smem = 3 * 24576;  // 72KB
    cudaFuncSetAttribute(gemm_hmma<false>, cudaFuncAttributeMaxDynamicSharedMemorySize, gemm_smem);
    cudaFuncSetAttribute(gemm_hmma<true>,  cudaFuncAttributeMaxDynamicSharedMemorySize, gemm_smem);
    const int attn_smem = 52224;  // Q(10240)+K(20480)+V(20480)+mneg(1024)
    cudaFuncSetAttribute(attn_kernel, cudaFuncAttributeMaxDynamicSharedMemorySize, attn_smem);

    // q prescale folds 1/sqrt(32) * log2(e)
    const float QSCALE = 0.17677669529663687f * 1.4426950408889634f;

    // 1) merged converts
    cvt_all_kernel<<<3072, 256>>>(msa, w_qkv, w_out, msa_h, wqkv_t, wout_t);

    // 2) pair bias (log2e-scaled), [h][q][k]
    pair_bias_kernel<<<8192, 256>>>(pair, w_pb, b_pb, bias_ptr);

    // 3) QKV GEMM (q prescaled)
    gemm_hmma<false><<<dim3(6, 512), 256, gemm_smem>>>(msa_h, wqkv_t, qkv_h, nullptr, nullptr,
                                                       768, QSCALE);

    // 4) attention  <-- profile slot
    attn_kernel<<<NSEQ * HEADS * 2, 128, attn_smem>>>(mask, qkv_h, bias_ptr, att_h);

    // 5) out-projection
    gemm_hmma<true><<<dim3(2, 512), 256, gemm_smem>>>(att_h, wout_t, nullptr, out, b_out,
                                                      256, 1.0f);
}

// round 17
// speedup vs baseline: 1.0171x; 1.0171x over previous
#include <cuda_runtime.h>
#include <cuda_fp16.h>
#include <cstdint>

#define LSEQ   256
#define NSEQ   128
#define DMODEL 256
#define HEADS  8
#define DHEAD  32
#define PDIM   128
#define MROWS  (NSEQ * LSEQ)   // 32768

// ---------------------------------------------------------------------------
// Scratch (device globals; allocation-free, graph-capture safe)
// ---------------------------------------------------------------------------
__device__ __align__(16) __half g_msa_h[MROWS * DMODEL];        // fp16 msa [32768][256]
__device__ __align__(16) __half g_wqkv_t[3 * DMODEL * DMODEL];  // [768][256]  (N-major, K contiguous)
__device__ __align__(16) __half g_wout_t[DMODEL * DMODEL];      // [256][256]
__device__ __align__(16) __half g_qkv_h[MROWS * 3 * DMODEL];    // [32768][768]  (q prescaled by scale*log2e)
__device__ __align__(16) __half g_att_h[MROWS * DMODEL];        // [32768][256]
__device__ float g_bias[HEADS * LSEQ * LSEQ];                   // [h][q][k]  (already * log2e)

// ---------------------------------------------------------------------------
// helpers
// ---------------------------------------------------------------------------
__device__ __forceinline__ uint32_t smem_u32(const void* p) {
    uint32_t a;
    asm("{ .reg .u64 t; cvta.to.shared.u64 t, %1; cvt.u32.u64 %0, t; }" : "=r"(a) : "l"(p));
    return a;
}

#define LDMX4(r0, r1, r2, r3, addr)                                           \
    asm volatile("ldmatrix.sync.aligned.m8n8.x4.shared.b16 {%0,%1,%2,%3}, [%4];" \
                 : "=r"(r0), "=r"(r1), "=r"(r2), "=r"(r3) : "r"(addr))

#define LDMX4T(r0, r1, r2, r3, addr)                                          \
    asm volatile("ldmatrix.sync.aligned.m8n8.x4.trans.shared.b16 {%0,%1,%2,%3}, [%4];" \
                 : "=r"(r0), "=r"(r1), "=r"(r2), "=r"(r3) : "r"(addr))

__device__ __forceinline__ void mma16816(float* c, const uint32_t* a, const uint32_t* b) {
    asm volatile("mma.sync.aligned.m16n8k16.row.col.f32.f16.f16.f32 "
                 "{%0,%1,%2,%3}, {%4,%5,%6,%7}, {%8,%9}, {%0,%1,%2,%3};"
                 : "+f"(c[0]), "+f"(c[1]), "+f"(c[2]), "+f"(c[3])
                 : "r"(a[0]), "r"(a[1]), "r"(a[2]), "r"(a[3]), "r"(b[0]), "r"(b[1]));
}

#define CP_ASYNC16(dst, src) \
    asm volatile("cp.async.cg.shared.global [%0], [%1], 16;" :: "r"(dst), "l"(src))
#define CP_COMMIT() asm volatile("cp.async.commit_group;" ::: "memory")
#define CP_WAIT(n)  asm volatile("cp.async.wait_group %0;" :: "n"(n) : "memory")

// ---------------------------------------------------------------------------
// HMMA GEMM, cp.async 3-stage pipeline: C[M,N] = A[M,256] @ Bt[N,256]^T.
// Block tile 64(M)x128(N); K chunked by 64. 8 warps each 16(M)x64(N).
// ---------------------------------------------------------------------------
template <bool FINAL>
__global__ void __launch_bounds__(256) gemm_hmma(
    const __half* __restrict__ A, const __half* __restrict__ Bt,
    __half* __restrict__ Ch, float* __restrict__ Cf,
    const float* __restrict__ bias, int ldc, float qscale)
{
    extern __shared__ __align__(16) char sm[];  // 3 stages x (A 8KB + B 16KB)

    const int tid = threadIdx.x;
    const int wid = tid >> 5, lane = tid & 31;
    const int m0 = blockIdx.y << 6;
    const int n0 = blockIdx.x << 7;
    const uint32_t smbase = smem_u32(sm);

    auto load_stage = [&](int s, int kc) {
        const uint32_t base = smbase + s * 24576;
#pragma unroll
        for (int i = 0; i < 6; i++) {
            const int idx = tid + i * 256;   // 0..1535
            if (idx < 512) {
                const int r = idx >> 3, c = idx & 7;
                const __half* src = A + (size_t)(m0 + r) * 256 + kc * 64 + c * 8;
                CP_ASYNC16(base + r * 128 + ((c ^ (r & 7)) << 4), src);
            } else {
                const int j = idx - 512;
                const int r = j >> 3, c = j & 7;
                const __half* src = Bt + (size_t)(n0 + r) * 256 + kc * 64 + c * 8;
                CP_ASYNC16(base + 8192 + r * 128 + ((c ^ (r & 7)) << 4), src);
            }
        }
        CP_COMMIT();
    };

    const int wm = (wid >> 1) << 4;    // 0,16,32,48
    const int wn = (wid & 1) << 6;     // 0,64
    const int a_row = (lane & 7) + ((lane >> 3) & 1) * 8;
    const int a_cadd = lane >> 4;
    const int b_row = (lane & 7) + ((lane >> 4) & 1) * 8;
    const int b_cadd = (lane >> 3) & 1;

    const int a_r = wm + a_row;
    int b_r[4];
#pragma unroll
    for (int j = 0; j < 4; j++) b_r[j] = wn + 16 * j + b_row;

    float acc[8][4];
#pragma unroll
    for (int j = 0; j < 8; j++)
#pragma unroll
        for (int t = 0; t < 4; t++) acc[j][t] = 0.f;

    auto compute_chunk = [&](int s) {
        const uint32_t baseA = smbase + s * 24576;
        const uint32_t baseB = baseA + 8192;
#pragma unroll
        for (int kk = 0; kk < 4; kk++) {
            const int k8 = kk * 2;
            uint32_t a[4];
            {
                const uint32_t addr = baseA + a_r * 128 +
                                      (((k8 + a_cadd) ^ (a_r & 7)) << 4);
                LDMX4(a[0], a[1], a[2], a[3], addr);
            }
            uint32_t b[8][2];
#pragma unroll
            for (int j = 0; j < 4; j++) {
                const uint32_t addr = baseB + b_r[j] * 128 +
                                      (((k8 + b_cadd) ^ (b_r[j] & 7)) << 4);
                LDMX4(b[2 * j][0], b[2 * j][1], b[2 * j + 1][0], b[2 * j + 1][1], addr);
            }
#pragma unroll
            for (int j = 0; j < 8; j++)
                mma16816(acc[j], a, b[j]);
        }
    };

    load_stage(0, 0);
    load_stage(1, 1);
    load_stage(2, 2);

    CP_WAIT(2); __syncthreads();
    compute_chunk(0);
    __syncthreads();
    load_stage(0, 3);

    CP_WAIT(2); __syncthreads();
    compute_chunk(1);

    CP_WAIT(1); __syncthreads();
    compute_chunk(2);

    CP_WAIT(0); __syncthreads();
    compute_chunk(0);

    const int tr = lane >> 2;
    const int tc = (lane & 3) * 2;
    const int row = m0 + wm + tr;
#pragma unroll
    for (int j = 0; j < 8; j++) {
        const int col = n0 + wn + 8 * j + tc;
        if (FINAL) {
            const float b0 = __ldg(&bias[col]), b1 = __ldg(&bias[col + 1]);
            float2 v0 = make_float2(acc[j][0] + b0, acc[j][1] + b1);
            float2 v1 = make_float2(acc[j][2] + b0, acc[j][3] + b1);
            *(float2*)(Cf + (size_t)row * ldc + col) = v0;
            *(float2*)(Cf + (size_t)(row + 8) * ldc + col) = v1;
        } else {
            const float qs = (col < 256) ? qscale : 1.0f;
            __half2 h0 = __floats2half2_rn(acc[j][0] * qs, acc[j][1] * qs);
            __half2 h1 = __floats2half2_rn(acc[j][2] * qs, acc[j][3] * qs);
            *(__half2*)(Ch + (size_t)row * ldc + col) = h0;
            *(__half2*)(Ch + (size_t)(row + 8) * ldc + col) = h1;
        }
    }
}

// ---------------------------------------------------------------------------
// Merged conversion kernel: blocks [0,2048) convert msa (fp32->fp16),
// blocks [2048,2816) transpose+convert w_qkv, blocks [2816,3072) w_out.
// ---------------------------------------------------------------------------
__global__ void __launch_bounds__(256) cvt_all_kernel(
    const float* __restrict__ msa, const float* __restrict__ w_qkv,
    const float* __restrict__ w_out, __half* __restrict__ msa_h,
    __half* __restrict__ wqkv_t, __half* __restrict__ wout_t)
{
    const int b = blockIdx.x;
    const int tid = threadIdx.x;
    if (b < 2048) {
        const float4* in = (const float4*)msa;
        __half2* out = (__half2*)msa_h;
        const int n4 = MROWS * DMODEL / 4;   // 2097152
#pragma unroll
        for (int it = 0; it < 4; it++) {
            const int i = b * 256 + tid + it * 524288;
            if (i < n4) {
                float4 v = in[i];
                out[2 * i]     = __floats2half2_rn(v.x, v.y);
                out[2 * i + 1] = __floats2half2_rn(v.z, v.w);
            }
        }
    } else if (b < 2816) {
        const int idx = (b - 2048) * 256 + tid;   // < 768*256 = 196608
        const int n = idx >> 8, k = idx & 255;
        wqkv_t[idx] = __float2half(w_qkv[k * (3 * DMODEL) + n]);
    } else {
        const int idx = (b - 2816) * 256 + tid;   // < 65536
        const int n = idx >> 8, k = idx & 255;
        wout_t[idx] = __float2half(w_out[k * DMODEL + n]);
    }
}

// ---------------------------------------------------------------------------
// pair_bias: bias[h][q][k] = (sum_p pair[q][k][p] * w_pb[p][h] + b_pb[h]) * log2e
// ---------------------------------------------------------------------------
__global__ void __launch_bounds__(256) pair_bias_kernel(
    const float* __restrict__ pair, const float* __restrict__ w_pb,
    const float* __restrict__ b_pb, float* __restrict__ bias_out)
{
    __shared__ float w[PDIM * HEADS];
    __shared__ float bb[HEADS];
    const int tid = threadIdx.x;
    for (int i = tid; i < PDIM * HEADS; i += 256) w[i] = w_pb[i];
    if (tid < HEADS) bb[tid] = b_pb[tid];
    __syncthreads();

    const int warp = (blockIdx.x << 3) + (tid >> 5);
    const int lane = tid & 31;
    const int q = warp >> 8;
    const int k = warp & 255;

    float4 p = *(const float4*)(pair + ((size_t)(q << 8) + k) * PDIM + (lane << 2));
    const int p0 = lane << 2;
    const float LOG2E = 1.4426950408889634f;

    float res[HEADS];
#pragma unroll
    for (int h = 0; h < HEADS; h++) {
        float s = p.x * w[(p0 + 0) * HEADS + h]
                + p.y * w[(p0 + 1) * HEADS + h]
                + p.z * w[(p0 + 2) * HEADS + h]
                + p.w * w[(p0 + 3) * HEADS + h];
#pragma unroll
        for (int off = 16; off; off >>= 1)
            s += __shfl_xor_sync(0xFFFFFFFFu, s, off);
        res[h] = (s + bb[h]) * LOG2E;
    }
    if (lane == 0) {
#pragma unroll
        for (int h = 0; h < HEADS; h++)
            bias_out[((size_t)(h << 8) + q) * LSEQ + k] = res[h];
    }
}

// ---------------------------------------------------------------------------
// Attention v8: v6 shape (64 q-rows/CTA, 4 warps, 32-key chunks, log2-domain
// softmax, additive mask) but with 64B row pitch + XOR swizzle
//   off(l,c) = l*64 + ((c ^ ((l>>1)&3)) << 4)
// -> smem 47.1KB -> 37KB -> 6 CTAs/SM (occupancy was the measured limiter:
// occ 17-24%, no pipe >52%).
// ---------------------------------------------------------------------------
__global__ void __launch_bounds__(128) attn_kernel(
    const int* __restrict__ mask, const __half* __restrict__ qkv,
    const float* __restrict__ bias, __half* __restrict__ outh)
{
    extern __shared__ __align__(16) char smc[];
    char* Qs = smc;                    // 64 rows x 64B (swizzled)
    char* Ks = smc + 4096;             // 256 rows x 64B
    char* Vs = smc + 20480;            // 256 rows x 64B
    float* mneg = (float*)(smc + 36864);  // 256 floats: 0 or -16384

    const int bx = blockIdx.x;
    const int n = bx >> 5;
    const int h = (bx >> 2) & 7;
    const int qb = (bx & 3) << 6;
    const int tid = threadIdx.x;
    const int wid = tid >> 5, lane = tid & 31;

    auto swz = [](int l, int c) { return l * 64 + ((c ^ ((l >> 1) & 3)) << 4); };

    const __half* basep = qkv + (size_t)(n * LSEQ) * 768 + h * DHEAD;
    for (int u = tid; u < 1024; u += 128) {
        const int l = u >> 2, c = u & 3;
        const __half* r = basep + (size_t)l * 768 + c * 8;
        const int d = swz(l, c);
        *(uint4*)(Ks + d) = *(const uint4*)(r + 256);
        *(uint4*)(Vs + d) = *(const uint4*)(r + 512);
    }
    for (int u = tid; u < 256; u += 128) {
        const int l = u >> 2, c = u & 3;
        *(uint4*)(Qs + swz(l, c)) = *(const uint4*)(basep + (size_t)(qb + l) * 768 + c * 8);
    }
    mneg[tid] = mask[n * LSEQ + tid] ? 0.0f : -16384.0f;
    mneg[tid + 128] = mask[n * LSEQ + tid + 128] ? 0.0f : -16384.0f;
    __syncthreads();

    const uint32_t Qa = smem_u32(Qs), Ka = smem_u32(Ks), Va = smem_u32(Vs);
    const int wq0 = wid * 16;
    const int a_row = (lane & 7) + ((lane >> 3) & 1) * 8;
    const int a_c = lane >> 4;
    const int b_row = (lane & 7) + ((lane >> 4) & 1) * 8;
    const int b_c = (lane >> 3) & 1;
    const int tr = lane >> 2, tc = (lane & 3) * 2;

    uint32_t aq[2][4];
#pragma unroll
    for (int kt = 0; kt < 2; kt++) {
        const uint32_t addr = Qa + swz(wq0 + a_row, kt * 2 + a_c);
        LDMX4(aq[kt][0], aq[kt][1], aq[kt][2], aq[kt][3], addr);
    }

    float o[4][4];
#pragma unroll
    for (int nt = 0; nt < 4; nt++)
#pragma unroll
        for (int t = 0; t < 4; t++) o[nt][t] = 0.f;
    float rsum[2] = {0.f, 0.f};
    float rmax[2] = {-1e30f, -1e30f};

    const float* bias_h = bias + (size_t)h * LSEQ * LSEQ;  // [q][k]
    const float* br0 = bias_h + (size_t)(qb + wq0 + tr) * 256;
    const float* br1 = br0 + 8 * 256;

#pragma unroll
    for (int j = 0; j < 8; j++) {
        const int kb = j * 32;

        float2 b0[4], b1[4], mn[4];
#pragma unroll
        for (int nn = 0; nn < 4; nn++) {
            const int kc = kb + nn * 8 + tc;
            b0[nn] = *(const float2*)(br0 + kc);
            b1[nn] = *(const float2*)(br1 + kc);
            mn[nn] = *(float2*)&mneg[kc];
        }

        uint32_t bk[2][2][4];
#pragma unroll
        for (int kg = 0; kg < 2; kg++)
#pragma unroll
            for (int kt = 0; kt < 2; kt++) {
                const uint32_t addr = Ka + swz(kb + kg * 16 + b_row, kt * 2 + b_c);
                LDMX4(bk[kg][kt][0], bk[kg][kt][1], bk[kg][kt][2], bk[kg][kt][3], addr);
            }

        uint32_t bv[2][4][2];
#pragma unroll
        for (int kg = 0; kg < 2; kg++)
#pragma unroll
            for (int dh = 0; dh < 2; dh++) {
                uint32_t r0, r1, r2, r3;
                const uint32_t addr = Va + swz(kb + kg * 16 + a_row, dh * 2 + a_c);
                LDMX4T(r0, r1, r2, r3, addr);
                bv[kg][dh * 2][0] = r0;     bv[kg][dh * 2][1] = r1;
                bv[kg][dh * 2 + 1][0] = r2; bv[kg][dh * 2 + 1][1] = r3;
            }

        float s[4][4];
#pragma unroll
        for (int nn = 0; nn < 4; nn++) {
#pragma unroll
            for (int t = 0; t < 4; t++) s[nn][t] = 0.f;
#pragma unroll
            for (int kt = 0; kt < 2; kt++)
                mma16816(s[nn], aq[kt], &bk[nn >> 1][kt][(nn & 1) * 2]);
        }

        float cmax[2] = {-1e30f, -1e30f};
#pragma unroll
        for (int nn = 0; nn < 4; nn++) {
            s[nn][0] += b0[nn].x + mn[nn].x;
            s[nn][1] += b0[nn].y + mn[nn].y;
            s[nn][2] += b1[nn].x + mn[nn].x;
            s[nn][3] += b1[nn].y + mn[nn].y;
            cmax[0] = fmaxf(cmax[0], fmaxf(s[nn][0], s[nn][1]));
            cmax[1] = fmaxf(cmax[1], fmaxf(s[nn][2], s[nn][3]));
        }

        float sf[2];
#pragma unroll
        for (int r = 0; r < 2; r++) {
            float v = cmax[r];
            v = fmaxf(v, __shfl_xor_sync(0xFFFFFFFFu, v, 1));
            v = fmaxf(v, __shfl_xor_sync(0xFFFFFFFFu, v, 2));
            const float mnew = fmaxf(rmax[r], v);
            sf[r] = exp2f(rmax[r] - mnew);
            rmax[r] = mnew;
            rsum[r] *= sf[r];
        }
#pragma unroll
        for (int nt = 0; nt < 4; nt++) {
            o[nt][0] *= sf[0]; o[nt][1] *= sf[0];
            o[nt][2] *= sf[1]; o[nt][3] *= sf[1];
        }

        uint32_t ap[2][4];
#pragma unroll
        for (int nn = 0; nn < 4; nn++) {
            float p0 = exp2f(s[nn][0] - rmax[0]);
            float p1 = exp2f(s[nn][1] - rmax[0]);
            float p2 = exp2f(s[nn][2] - rmax[1]);
            float p3 = exp2f(s[nn][3] - rmax[1]);
            rsum[0] += p0 + p1;
            rsum[1] += p2 + p3;
            __half2 h01 = __floats2half2_rn(p0, p1);
            __half2 h23 = __floats2half2_rn(p2, p3);
            const int kg = nn >> 1, half_ = (nn & 1) * 2;
            ap[kg][half_ + 0] = *(uint32_t*)&h01;
            ap[kg][half_ + 1] = *(uint32_t*)&h23;
        }

#pragma unroll
        for (int nt = 0; nt < 4; nt++)
#pragma unroll
            for (int kg = 0; kg < 2; kg++)
                mma16816(o[nt], ap[kg], bv[kg][nt]);
    }

    float inv[2];
#pragma unroll
    for (int r = 0; r < 2; r++) {
        float v = rsum[r];
        v += __shfl_xor_sync(0xFFFFFFFFu, v, 1);
        v += __shfl_xor_sync(0xFFFFFFFFu, v, 2);
        inv[r] = (v > 0.f) ? (1.0f / v) : 0.f;
    }

    const size_t q0 = (size_t)(n * LSEQ + qb + wq0 + tr);
    const int dcol = h * DHEAD + tc;
#pragma unroll
    for (int nt = 0; nt < 4; nt++) {
        __half2 h0 = __floats2half2_rn(o[nt][0] * inv[0], o[nt][1] * inv[0]);
        __half2 h1 = __floats2half2_rn(o[nt][2] * inv[1], o[nt][3] * inv[1]);
        *(__half2*)(outh + q0 * DMODEL + dcol + nt * 8) = h0;
        *(__half2*)(outh + (q0 + 8) * DMODEL + dcol + nt * 8) = h1;
    }
}

// ---------------------------------------------------------------------------
// Launch: single stream, 5 kernels; attn stays in profile slot #4.
// ---------------------------------------------------------------------------
extern "C" void kernel_launch(void* const* d_in, const int* in_sizes, int n_in,
                              void* d_out, int out_size)
{
    const float* msa   = (const float*)d_in[0];
    const float* pair  = (const float*)d_in[1];
    const int*   mask  = (const int*)d_in[2];
    const float* w_qkv = (const float*)d_in[3];
    const float* w_pb  = (const float*)d_in[4];
    const float* b_pb  = (const float*)d_in[5];
    const float* w_out = (const float*)d_in[6];
    const float* b_out = (const float*)d_in[7];
    float* out = (float*)d_out;

    __half *msa_h, *wqkv_t, *wout_t, *qkv_h, *att_h;
    float* bias_ptr;
    cudaGetSymbolAddress((void**)&msa_h,   g_msa_h);
    cudaGetSymbolAddress((void**)&wqkv_t,  g_wqkv_t);
    cudaGetSymbolAddress((void**)&wout_t,  g_wout_t);
    cudaGetSymbolAddress((void**)&qkv_h,   g_qkv_h);
    cudaGetSymbolAddress((void**)&att_h,   g_att_h);
    cudaGetSymbolAddress((void**)&bias_ptr, g_bias);

    const int gemm_smem = 3 * 24576;  // 72KB
    cudaFuncSetAttribute(gemm_hmma<false>, cudaFuncAttributeMaxDynamicSharedMemorySize, gemm_smem);
    cudaFuncSetAttribute(gemm_hmma<true>,  cudaFuncAttributeMaxDynamicSharedMemorySize, gemm_smem);
    const int attn_smem = 37888;  // Q 4096 + K 16384 + V 16384 + mneg 1024
    cudaFuncSetAttribute(attn_kernel, cudaFuncAttributeMaxDynamicSharedMemorySize, attn_smem);

    // q prescale folds 1/sqrt(32) * log2(e)
    const float QSCALE = 0.17677669529663687f * 1.4426950408889634f;

    // 1) merged converts
    cvt_all_kernel<<<3072, 256>>>(msa, w_qkv, w_out, msa_h, wqkv_t, wout_t);

    // 2) pair bias (log2e-scaled), [h][q][k]
    pair_bias_kernel<<<8192, 256>>>(pair, w_pb, b_pb, bias_ptr);

    // 3) QKV GEMM (q prescaled)
    gemm_hmma<false><<<dim3(6, 512), 256, gemm_smem>>>(msa_h, wqkv_t, qkv_h, nullptr, nullptr,
                                                       768, QSCALE);

    // 4) attention  <-- profile slot
    attn_kernel<<<NSEQ * HEADS * 4, 128, attn_smem>>>(mask, qkv_h, bias_ptr, att_h);

    // 5) out-projection
    gemm_hmma<true><<<dim3(2, 512), 256, gemm_smem>>>(att_h, wout_t, nullptr, out, b_out,
                                                      256, 1.0f);
}